// round 9
// baseline (speedup 1.0000x reference)
#include <cuda_runtime.h>
#include <cstdint>

// SplineActivation: y[b,w] = clamped cubic B-spline (16 uniform knots on [-3,3],
// degree 3) of x[b,w], per-channel coefficients coefs[w, 0..17].
//
// Round-9: single fused kernel. R4/R6/R8 showed the eval dataflow floor is
// ~16.8us and insensitive to MLP/occupancy/store-path; R8 showed in-loop
// barriers actively hurt. So: keep R6's barrier-free eval loop verbatim and
// reclaim the measured 0.73us of build-kernel + launch-gap tax by building
// each CTA's 128-channel table slice in its own prologue:
//   coefs slice (9KB) staged coalesced into smem -> threads 0-59 compute the
//   60 fixed interval-conversion cubics (FP32, redundant per CTA, cheap) ->
//   each thread emits ~7.5 table entries (4 LDS + 16 FMA each) into the tile.
// Plus read-once/write-once cache hints (__ldcs/__stcs) on the 64MB stream.

#define W_TOTAL  1024
#define B_TOTAL  8192
#define NB_IV    15
#define CH       128
#define BD       256
#define R        8            // rows per thread per iteration (16 rows/CTA-iter)
#define N_CTRL   18
#define GY       92           // 8 x 92 = 736 CTAs ~= 5 per SM

__global__ __launch_bounds__(BD, 5)
void spline_fused_kernel(const float* __restrict__ X,
                         const float* __restrict__ coefs,
                         float* __restrict__ Y) {
    __shared__ float4 sp[NB_IV][CH];          // 30,720 B  poly tile
    __shared__ float4 M[NB_IV * 4];           //    960 B  conversion cubics
    __shared__ float  cfs[CH * N_CTRL];       //  9,216 B  coefs slice

    const int t  = threadIdx.x;
    const int c0 = blockIdx.x * CH;

    // ---- Prologue 1: stage coefs slice, coalesced (9 floats/thread). ----
    {
        const float* src = coefs + (size_t)c0 * N_CTRL;
        for (int i = t; i < CH * N_CTRL; i += BD)
            cfs[i] = __ldg(&src[i]);
    }

    // ---- Prologue 2: threads 0..59 compute the 15x4 conversion cubics. ----
    if (t < NB_IV * 4) {
        const int k = t >> 2;
        const int j = t & 3;

        float tk[22];
#pragma unroll
        for (int m = 0; m < 16; m++)
            tk[3 + m] = (float)(-3.0 + (double)m * (6.0 / 15.0));
        tk[0] = tk[1] = tk[2] = tk[3];
        tk[19] = tk[20] = tk[21] = tk[18];

        const int   kg    = k + 3;
        const float x0    = tk[kg];
        const float delta = (tk[kg + 1] - tk[kg]) * (1.0f / 3.0f);
        const float Kev   = fmaf((float)k, 0.4f, -3.0f);

        float f[4];
#pragma unroll
        for (int m = 0; m < 4; m++) {
            float x = x0 + delta * (float)m;
            float left[3], right[3];
#pragma unroll
            for (int i2 = 1; i2 <= 3; i2++) {
                left [i2 - 1] = x - tk[kg + 1 - i2];
                right[i2 - 1] = tk[kg + i2] - x;
            }
            float N[4];
            N[0] = 1.0f;
#pragma unroll
            for (int jj = 1; jj <= 3; jj++) {
                float saved = 0.0f;
#pragma unroll
                for (int r = 0; r < jj; r++) {
                    float temp = N[r] / (right[r] + left[jj - 1 - r]);
                    N[r] = saved + right[r] * temp;
                    saved = left[jj - 1 - r] * temp;
                }
                N[jj] = saved;
            }
            f[m] = N[j];
        }

        const float id = 1.0f / delta;
        const float d1 = (f[1] - f[0]) * id;
        const float d2 = (f[2] - 2.0f * f[1] + f[0]) * (0.5f * id * id);
        const float d3 = (f[3] - 3.0f * f[2] + 3.0f * f[1] - f[0])
                         * ((1.0f / 6.0f) * id * id * id);
        const float a0 = f[0];
        const float a1 = d1 - delta * d2 + 2.0f * delta * delta * d3;
        const float a2 = d2 - 3.0f * delta * d3;
        const float a3 = d3;

        const float s0 = x0 - Kev;
        const float b3 = a3;
        const float b2 = a2 - 3.0f * a3 * s0;
        const float b1 = a1 - 2.0f * a2 * s0 + 3.0f * a3 * s0 * s0;
        const float b0 = a0 - a1 * s0 + a2 * s0 * s0 - a3 * s0 * s0 * s0;

        M[t] = make_float4(b0, b1, b2, b3);
    }
    __syncthreads();

    // ---- Prologue 3: build this CTA's poly tile (7.5 entries/thread). ----
    for (int i = t; i < NB_IV * CH; i += BD) {
        const int k   = i >> 7;
        const int chl = i & (CH - 1);
        float4 acc = make_float4(0.f, 0.f, 0.f, 0.f);
#pragma unroll
        for (int j = 0; j < 4; j++) {
            float  cf = cfs[chl * N_CTRL + k + j];
            float4 m  = M[k * 4 + j];
            acc.x = fmaf(cf, m.x, acc.x);
            acc.y = fmaf(cf, m.y, acc.y);
            acc.z = fmaf(cf, m.z, acc.z);
            acc.w = fmaf(cf, m.w, acc.w);
        }
        sp[k][chl] = acc;
    }
    __syncthreads();

    // ---- Main loop: identical structure to R6 (proven fastest). ----
    const int ch = t & (CH - 1);
    const int rl = t >> 7;                    // 0..1
    const int rstep = gridDim.y * 2 * R;

    for (int base = blockIdx.y * 2 * R; base < B_TOTAL; base += rstep) {
        const int r0 = base + rl * R;         // this thread: rows r0 .. r0+7
        const float* xp = X + (size_t)r0 * W_TOTAL + c0 + ch;
        float*       yp = Y + (size_t)r0 * W_TOTAL + c0 + ch;

        float xv[R];
#pragma unroll
        for (int q = 0; q < R; q++) xv[q] = __ldcs(&xp[q * W_TOTAL]);

#pragma unroll
        for (int q = 0; q < R; q++) {
            float x  = xv[q];
            float fi = floorf(fmaf(x, 2.5f, 7.5f));
            fi       = fminf(fmaxf(fi, 0.0f), 14.0f);
            int   k  = (int)fi;
            float s  = x - fmaf(fi, 0.4f, -3.0f);
            float4 p = sp[k][ch];
            xv[q] = fmaf(fmaf(fmaf(p.w, s, p.z), s, p.y), s, p.x);
        }

#pragma unroll
        for (int q = 0; q < R; q++) __stcs(&yp[q * W_TOTAL], xv[q]);
    }
}

// ---------------------------------------------------------------------------
extern "C" void kernel_launch(void* const* d_in, const int* in_sizes, int n_in,
                              void* d_out, int out_size) {
    const float* X     = (const float*)d_in[0];
    const float* coefs = (const float*)d_in[1];
    if (n_in >= 2 && in_sizes[0] < in_sizes[1]) {   // identify by size
        X     = (const float*)d_in[1];
        coefs = (const float*)d_in[0];
    }
    float* Y = (float*)d_out;

    dim3 grid(W_TOTAL / CH, GY);              // 8 x 92 = 736 CTAs
    spline_fused_kernel<<<grid, BD>>>(X, coefs, Y);
}

// round 10
// speedup vs baseline: 1.1198x; 1.1198x over previous
#include <cuda_runtime.h>
#include <cstdint>

// SplineActivation: y[b,w] = clamped cubic B-spline (16 uniform knots on [-3,3],
// degree 3) of x[b,w], per-channel coefficients coefs[w, 0..17].
//
// Round-10: R4/R6 invariant (16.768us, 2045GB/s at both MLP=4 and MLP=8) says
// the X read is capped by the per-SM LDG in-flight queue, not by warp-level
// MLP. cp.async (LDGSTS) has no observed depth cap and bypasses the register
// scoreboard, so X is staged through a 3-stage 8KB cp.async pipeline into
// smem; compute reads x via conflict-free LDS.32. Table gather (conflict-free
// LDS.128) + Horner + coalesced STG.32 unchanged from the proven R6 loop.
// Build kernel unchanged from R6 (fused FP32 matrix+apply).

#define W_TOTAL  1024
#define B_TOTAL  8192
#define NB_IV    15
#define CH       128
#define BD       256
#define TROWS    16          // rows per tile
#define STAGES   3
#define N_CTRL   18
#define GY       74          // 8 x 74 = 592 CTAs = 4 per SM
#define N_TILES  (B_TOTAL / TROWS)   // 512

__device__ float4 g_poly[NB_IV * W_TOTAL];   // [interval][channel] monomial cubic

// ---------------------------------------------------------------------------
// Fused build (unchanged): 15x4 conversion cubics in smem, one g_poly entry
// per thread. Grid 60 x 256.
// ---------------------------------------------------------------------------
__global__ __launch_bounds__(BD)
void build_poly_kernel(const float* __restrict__ coefs) {
    __shared__ float4 M[NB_IV * 4];
    const int t = threadIdx.x;

    if (t < NB_IV * 4) {
        const int k = t >> 2;
        const int j = t & 3;

        float tk[22];
#pragma unroll
        for (int m = 0; m < 16; m++)
            tk[3 + m] = (float)(-3.0 + (double)m * (6.0 / 15.0));
        tk[0] = tk[1] = tk[2] = tk[3];
        tk[19] = tk[20] = tk[21] = tk[18];

        const int   kg    = k + 3;
        const float x0    = tk[kg];
        const float delta = (tk[kg + 1] - tk[kg]) * (1.0f / 3.0f);
        const float Kev   = fmaf((float)k, 0.4f, -3.0f);

        float f[4];
#pragma unroll
        for (int m = 0; m < 4; m++) {
            float x = x0 + delta * (float)m;
            float left[3], right[3];
#pragma unroll
            for (int i2 = 1; i2 <= 3; i2++) {
                left [i2 - 1] = x - tk[kg + 1 - i2];
                right[i2 - 1] = tk[kg + i2] - x;
            }
            float N[4];
            N[0] = 1.0f;
#pragma unroll
            for (int jj = 1; jj <= 3; jj++) {
                float saved = 0.0f;
#pragma unroll
                for (int r = 0; r < jj; r++) {
                    float temp = N[r] / (right[r] + left[jj - 1 - r]);
                    N[r] = saved + right[r] * temp;
                    saved = left[jj - 1 - r] * temp;
                }
                N[jj] = saved;
            }
            f[m] = N[j];
        }

        const float id = 1.0f / delta;
        const float d1 = (f[1] - f[0]) * id;
        const float d2 = (f[2] - 2.0f * f[1] + f[0]) * (0.5f * id * id);
        const float d3 = (f[3] - 3.0f * f[2] + 3.0f * f[1] - f[0])
                         * ((1.0f / 6.0f) * id * id * id);
        const float a0 = f[0];
        const float a1 = d1 - delta * d2 + 2.0f * delta * delta * d3;
        const float a2 = d2 - 3.0f * delta * d3;
        const float a3 = d3;

        const float s0 = x0 - Kev;
        const float b3 = a3;
        const float b2 = a2 - 3.0f * a3 * s0;
        const float b1 = a1 - 2.0f * a2 * s0 + 3.0f * a3 * s0 * s0;
        const float b0 = a0 - a1 * s0 + a2 * s0 * s0 - a3 * s0 * s0 * s0;

        M[t] = make_float4(b0, b1, b2, b3);
    }
    __syncthreads();

    const int idx = blockIdx.x * BD + t;
    const int c   = idx & (W_TOTAL - 1);
    const int k   = idx >> 10;

    float4 acc = make_float4(0.f, 0.f, 0.f, 0.f);
#pragma unroll
    for (int j = 0; j < 4; j++) {
        float  cf = __ldg(&coefs[c * N_CTRL + k + j]);
        float4 m  = M[k * 4 + j];
        acc.x = fmaf(cf, m.x, acc.x);
        acc.y = fmaf(cf, m.y, acc.y);
        acc.z = fmaf(cf, m.z, acc.z);
        acc.w = fmaf(cf, m.w, acc.w);
    }
    g_poly[k * W_TOTAL + c] = acc;
}

// ---------------------------------------------------------------------------
// cp.async helper: issue one 16-row x 128-ch tile (512 x 16B chunks, 2/thread).
// ---------------------------------------------------------------------------
__device__ __forceinline__ void issue_tile(const float* __restrict__ X,
                                           float* xs_stage, int tile, int c0,
                                           int t) {
    const float* src_base = X + (size_t)tile * TROWS * W_TOTAL + c0;
#pragma unroll
    for (int rep = 0; rep < 2; rep++) {
        int i   = t + rep * BD;          // 0..511
        int row = i >> 5;
        int seg = i & 31;
        const float* g = src_base + row * W_TOTAL + seg * 4;
        unsigned int saddr =
            (unsigned int)__cvta_generic_to_shared(xs_stage + row * CH + seg * 4);
        asm volatile("cp.async.cg.shared.global [%0], [%1], 16;"
                     :: "r"(saddr), "l"(g));
    }
}

// ---------------------------------------------------------------------------
// Hot kernel. Table staged from g_poly (as R6). X comes through a 3-stage
// cp.async pipeline (8KB/stage). Compute: conflict-free LDS.32 on x,
// conflict-free LDS.128 table gather, 3-FMA Horner, coalesced STG.32.
// ---------------------------------------------------------------------------
__global__ __launch_bounds__(BD, 4)
void spline_eval_kernel(const float* __restrict__ X, float* __restrict__ Y) {
    extern __shared__ __align__(16) char smem[];
    float4 (*sp)[CH] = (float4 (*)[CH])smem;                       // 30,720 B
    float*  xs       = (float*)(smem + NB_IV * CH * sizeof(float4)); // 3 x 8,192 B

    const int t  = threadIdx.x;
    const int c0 = blockIdx.x * CH;

    // Stage the poly tile (conflict-free layout, as R6).
    for (int i = t; i < NB_IV * CH; i += BD)
        ((float4*)sp)[i] = g_poly[(i >> 7) * W_TOTAL + c0 + (i & (CH - 1))];

    // Prime the pipeline.
    int next = blockIdx.y;
#pragma unroll
    for (int s = 0; s < STAGES; s++) {
        if (next < N_TILES) {
            issue_tile(X, xs + s * (TROWS * CH), next, c0, t);
            next += GY;
        }
        asm volatile("cp.async.commit_group;" ::: "memory");
    }

    const int ch = t & (CH - 1);
    const int rh = t >> 7;               // 0..1; rows rh, rh+2, ..., rh+14

    int cur = 0;
    for (int ti = blockIdx.y; ti < N_TILES; ti += GY) {
        asm volatile("cp.async.wait_group %0;" :: "n"(STAGES - 1) : "memory");
        __syncthreads();                 // stage 'cur' full (+ sp ready, iter 0)

        const float* xb = xs + cur * (TROWS * CH);
        float rv[TROWS / 2];
#pragma unroll
        for (int q = 0; q < TROWS / 2; q++) {
            float x  = xb[(rh + 2 * q) * CH + ch];
            float fi = floorf(fmaf(x, 2.5f, 7.5f));
            fi       = fminf(fmaxf(fi, 0.0f), 14.0f);
            int   k  = (int)fi;
            float s  = x - fmaf(fi, 0.4f, -3.0f);
            float4 p = sp[k][ch];
            rv[q] = fmaf(fmaf(fmaf(p.w, s, p.z), s, p.y), s, p.x);
        }

        float* yb = Y + (size_t)ti * TROWS * W_TOTAL + c0 + ch;
#pragma unroll
        for (int q = 0; q < TROWS / 2; q++)
            yb[(rh + 2 * q) * W_TOTAL] = rv[q];

        __syncthreads();                 // everyone done reading stage 'cur'
        if (next < N_TILES) {
            issue_tile(X, xs + cur * (TROWS * CH), next, c0, t);
            next += GY;
        }
        asm volatile("cp.async.commit_group;" ::: "memory");

        cur = cur + 1; if (cur == STAGES) cur = 0;
    }
}

// ---------------------------------------------------------------------------
extern "C" void kernel_launch(void* const* d_in, const int* in_sizes, int n_in,
                              void* d_out, int out_size) {
    const float* X     = (const float*)d_in[0];
    const float* coefs = (const float*)d_in[1];
    if (n_in >= 2 && in_sizes[0] < in_sizes[1]) {   // identify by size
        X     = (const float*)d_in[1];
        coefs = (const float*)d_in[0];
    }
    float* Y = (float*)d_out;

    build_poly_kernel<<<NB_IV * W_TOTAL / BD, BD>>>(coefs);   // 60 x 256

    const int smem_bytes = NB_IV * CH * (int)sizeof(float4)
                         + STAGES * TROWS * CH * (int)sizeof(float);  // 55,296
    cudaFuncSetAttribute(spline_eval_kernel,
                         cudaFuncAttributeMaxDynamicSharedMemorySize, smem_bytes);

    dim3 grid(W_TOTAL / CH, GY);         // 8 x 74 = 592 = 4 per SM
    spline_eval_kernel<<<grid, BD, smem_bytes>>>(X, Y);
}